// round 13
// baseline (speedup 1.0000x reference)
#include <cuda_runtime.h>
#include <cuda_fp16.h>
#include <cstdint>
#include <math.h>

// Problem constants
#define Bq     4
#define Lq     4096
#define Hq     1024
#define NHq    16
#define Wq     64
#define SHIFTq 32
#define FFq    4096
#define HDq    64
#define Mq     (Bq * Lq)   // 16384 rows

// ---------------------------------------------------------------------------
// Scratch (device globals)
// ---------------------------------------------------------------------------
__device__ float  g_xs  [(size_t)Mq * Hq];
__device__ float  g_xsum[(size_t)Mq * Hq];
__device__ __half g_qin [(size_t)Mq * Hq];
__device__ __half g_qkv [(size_t)Mq * 3 * Hq];
__device__ __half g_attn[(size_t)Mq * Hq];
__device__ __half g_z   [(size_t)Mq * Hq];
__device__ __half g_h1  [(size_t)Mq * FFq];
__device__ __half g_wqkv[(size_t)3 * Hq * Hq];
__device__ __half g_wo  [(size_t)Hq * Hq];
__device__ __half g_w1  [(size_t)FFq * Hq];
__device__ __half g_w2  [(size_t)Hq * FFq];

// ---------------------------------------------------------------------------
// Helpers
// ---------------------------------------------------------------------------
__device__ __forceinline__ uint32_t smem_u32(const void* p) {
    uint32_t a;
    asm("{ .reg .u64 t; cvta.to.shared.u64 t, %1; cvt.u32.u64 %0, t; }" : "=r"(a) : "l"(p));
    return a;
}

__device__ __forceinline__ void mma_f16(float c[4], const uint32_t a[4], const uint32_t b[2]) {
    asm volatile(
        "mma.sync.aligned.m16n8k16.row.col.f32.f16.f16.f32 "
        "{%0,%1,%2,%3}, {%4,%5,%6,%7}, {%8,%9}, {%0,%1,%2,%3};\n"
        : "+f"(c[0]), "+f"(c[1]), "+f"(c[2]), "+f"(c[3])
        : "r"(a[0]), "r"(a[1]), "r"(a[2]), "r"(a[3]), "r"(b[0]), "r"(b[1]));
}

#define LDSM_X4(r0, r1, r2, r3, addr) \
    asm volatile("ldmatrix.sync.aligned.m8n8.x4.shared.b16 {%0,%1,%2,%3}, [%4];" \
        : "=r"(r0), "=r"(r1), "=r"(r2), "=r"(r3) : "r"(addr))

#define CP_ASYNC16(dst, src) \
    asm volatile("cp.async.cg.shared.global [%0], [%1], 16;" :: "r"(dst), "l"(src))

__device__ __forceinline__ float gelu_exact(float v) {
    return 0.5f * v * (1.0f + erff(v * 0.70710678118654752f));
}

__device__ __forceinline__ void store2(float* p, float a, float b) {
    *reinterpret_cast<float2*>(p) = make_float2(a, b);
}
__device__ __forceinline__ void store2(__half* p, float a, float b) {
    *reinterpret_cast<__half2*>(p) = __floats2half2_rn(a, b);
}

__device__ __forceinline__ uint32_t packh2(float a, float b) {
    __half2 h = __floats2half2_rn(a, b);
    return *reinterpret_cast<uint32_t*>(&h);
}

// ---------------------------------------------------------------------------
// float -> half conversion, four arrays in one launch
// ---------------------------------------------------------------------------
__global__ void __launch_bounds__(256)
f2h4_kernel(const float* __restrict__ s0, __half* __restrict__ d0, int n0,
            const float* __restrict__ s1, __half* __restrict__ d1, int n1,
            const float* __restrict__ s2, __half* __restrict__ d2, int n2,
            const float* __restrict__ s3, __half* __restrict__ d3, int n3)
{
    int i = (blockIdx.x * 256 + threadIdx.x) * 4;
    const float* s; __half* d;
    if (i < n0) { s = s0; d = d0; }
    else {
        i -= n0;
        if (i < n1) { s = s1; d = d1; }
        else {
            i -= n1;
            if (i < n2) { s = s2; d = d2; }
            else { i -= n2; s = s3; d = d3; if (i >= n3) return; }
        }
    }
    float4 f = *reinterpret_cast<const float4*>(s + i);
    *reinterpret_cast<__half2*>(d + i)     = __floats2half2_rn(f.x, f.y);
    *reinterpret_cast<__half2*>(d + i + 2) = __floats2half2_rn(f.z, f.w);
}

// ---------------------------------------------------------------------------
// LayerNorm (+ roll read, + optional copy of rolled raw input); output half
// ---------------------------------------------------------------------------
__global__ void __launch_bounds__(256)
ln_kernel(const float* __restrict__ x, const float* __restrict__ g,
          const float* __restrict__ bb, float* __restrict__ xs_out,
          __half* __restrict__ y, int shift)
{
    const int row = blockIdx.x;
    const int b   = row >> 12;
    const int l   = row & (Lq - 1);
    const int sl  = (l + shift) & (Lq - 1);
    const float* px = x + ((size_t)(b * Lq + sl)) * Hq;

    const int t = threadIdx.x;
    float v[4];
    float s = 0.f, sq = 0.f;
#pragma unroll
    for (int i = 0; i < 4; i++) {
        v[i] = px[t + i * 256];
        s  += v[i];
        sq += v[i] * v[i];
    }
#pragma unroll
    for (int o = 16; o > 0; o >>= 1) {
        s  += __shfl_xor_sync(0xffffffffu, s,  o);
        sq += __shfl_xor_sync(0xffffffffu, sq, o);
    }
    __shared__ float ws[8], wq[8];
    const int lane = t & 31, warp = t >> 5;
    if (lane == 0) { ws[warp] = s; wq[warp] = sq; }
    __syncthreads();
    if (t == 0) {
        float S = 0.f, Q = 0.f;
#pragma unroll
        for (int w = 0; w < 8; w++) { S += ws[w]; Q += wq[w]; }
        float mu  = S * (1.0f / Hq);
        float var = Q * (1.0f / Hq) - mu * mu;
        ws[0] = mu;
        wq[0] = rsqrtf(var + 1e-5f);
    }
    __syncthreads();
    const float mu = ws[0], rstd = wq[0];

    __half* py = y + (size_t)row * Hq;
    float* pxs = xs_out ? xs_out + (size_t)row * Hq : nullptr;
#pragma unroll
    for (int i = 0; i < 4; i++) {
        int c = t + i * 256;
        float xv = v[i];
        py[c] = __float2half((xv - mu) * rstd * g[c] + bb[c]);
        if (pxs) pxs[c] = xv;
    }
}

// ---------------------------------------------------------------------------
// Tensor-core windowed attention (verified in R8)
// ---------------------------------------------------------------------------
constexpr int ATT_HEAD_BYTES = 24576;            // Q 8K + K 8K + Vt 8K
constexpr int ATT_SMEM = 2 * ATT_HEAD_BYTES;     // 49152

__global__ void __launch_bounds__(128)
attn_mma_kernel(const __half* __restrict__ qkv, __half* __restrict__ attn)
{
    extern __shared__ char asmem[];
    const uint32_t sb = smem_u32(asmem);
    const int bw = blockIdx.x;
    const int b  = bw >> 6, w = bw & 63;
    const int h0 = blockIdx.y * 2;
    const int rowbase = b * Lq + w * 64;
    const int t = threadIdx.x;

#pragma unroll
    for (int hh = 0; hh < 2; hh++) {
        const uint32_t qs = sb + hh * ATT_HEAD_BYTES;
        const uint32_t ks = qs + 8192;
#pragma unroll
        for (int i = 0; i < 4; i++) {
            int idx = t + i * 128;
            int row = idx >> 3, ch = idx & 7;
            uint32_t off = (uint32_t)(row * 128 + ch * 16);
            uint32_t sw = off ^ ((off >> 3) & 0x70);
            const __half* gq = qkv + (size_t)(rowbase + row) * 3072 + (h0 + hh) * 64 + ch * 8;
            CP_ASYNC16(qs + sw, gq);
            CP_ASYNC16(ks + sw, gq + 1024);
        }
    }
    asm volatile("cp.async.commit_group;" ::: "memory");

#pragma unroll
    for (int hh = 0; hh < 2; hh++) {
        char* vtp = asmem + hh * ATT_HEAD_BYTES + 16384;
#pragma unroll
        for (int i = 0; i < 4; i++) {
            int idx = t + i * 128;
            int c = idx >> 3, ch = idx & 7;
            const __half* gv = qkv + (size_t)(rowbase + c) * 3072 + 2048 + (h0 + hh) * 64 + ch * 8;
            uint4 v = *reinterpret_cast<const uint4*>(gv);
            const __half* hv = reinterpret_cast<const __half*>(&v);
#pragma unroll
            for (int j = 0; j < 8; j++) {
                int d = ch * 8 + j;
                uint32_t off = (uint32_t)(d * 128 + c * 2);
                uint32_t sw = off ^ ((off >> 3) & 0x70);
                *reinterpret_cast<__half*>(vtp + sw) = hv[j];
            }
        }
    }
    asm volatile("cp.async.wait_group 0;" ::: "memory");
    __syncthreads();

    const int warp = t >> 5, lane = t & 31;
    const int hh = warp >> 1, mh = warp & 1;
    const uint32_t qs = sb + hh * ATT_HEAD_BYTES;
    const uint32_t ks = qs + 8192;
    const uint32_t vt = qs + 16384;
    const int lrow = lane & 15, lseg = lane >> 4;
    const int gid = lane >> 2, tig = lane & 3;

    uint32_t qOff[2], qM[2], nOff[4], nM[4];
#pragma unroll
    for (int mt = 0; mt < 2; mt++) {
        int row = mh * 32 + mt * 16 + lrow;
        qOff[mt] = (uint32_t)(row * 128 + lseg * 16);
        qM[mt]   = (uint32_t)((row & 7) << 4);
    }
#pragma unroll
    for (int g = 0; g < 4; g++) {
        int row = g * 16 + lrow;
        nOff[g] = (uint32_t)(row * 128 + lseg * 16);
        nM[g]   = (uint32_t)((row & 7) << 4);
    }

    float S[2][8][4];
#pragma unroll
    for (int mt = 0; mt < 2; mt++)
#pragma unroll
        for (int nj = 0; nj < 8; nj++)
#pragma unroll
            for (int c = 0; c < 4; c++) S[mt][nj][c] = 0.f;

#pragma unroll
    for (int kt = 0; kt < 4; kt++) {
        uint32_t af[2][4], bf[8][2];
#pragma unroll
        for (int mt = 0; mt < 2; mt++)
            LDSM_X4(af[mt][0], af[mt][1], af[mt][2], af[mt][3],
                    qs + ((qOff[mt] + kt * 32) ^ qM[mt]));
#pragma unroll
        for (int g = 0; g < 4; g++) {
            uint32_t r0, r1, r2, r3;
            LDSM_X4(r0, r1, r2, r3, ks + ((nOff[g] + kt * 32) ^ nM[g]));
            bf[2 * g][0] = r0; bf[2 * g][1] = r2;
            bf[2 * g + 1][0] = r1; bf[2 * g + 1][1] = r3;
        }
#pragma unroll
        for (int mt = 0; mt < 2; mt++)
#pragma unroll
            for (int nj = 0; nj < 8; nj++)
                mma_f16(S[mt][nj], af[mt], bf[nj]);
    }

    float mx[2][2], sum[2][2];
#pragma unroll
    for (int mt = 0; mt < 2; mt++) { mx[mt][0] = -1e30f; mx[mt][1] = -1e30f; }
#pragma unroll
    for (int mt = 0; mt < 2; mt++)
#pragma unroll
        for (int nj = 0; nj < 8; nj++) {
#pragma unroll
            for (int c = 0; c < 4; c++) S[mt][nj][c] *= 0.125f;
            mx[mt][0] = fmaxf(mx[mt][0], fmaxf(S[mt][nj][0], S[mt][nj][1]));
            mx[mt][1] = fmaxf(mx[mt][1], fmaxf(S[mt][nj][2], S[mt][nj][3]));
        }
#pragma unroll
    for (int mt = 0; mt < 2; mt++)
#pragma unroll
        for (int rr = 0; rr < 2; rr++) {
            mx[mt][rr] = fmaxf(mx[mt][rr], __shfl_xor_sync(0xffffffffu, mx[mt][rr], 1));
            mx[mt][rr] = fmaxf(mx[mt][rr], __shfl_xor_sync(0xffffffffu, mx[mt][rr], 2));
        }
#pragma unroll
    for (int mt = 0; mt < 2; mt++) { sum[mt][0] = 0.f; sum[mt][1] = 0.f; }
#pragma unroll
    for (int mt = 0; mt < 2; mt++)
#pragma unroll
        for (int nj = 0; nj < 8; nj++) {
            S[mt][nj][0] = expf(S[mt][nj][0] - mx[mt][0]);
            S[mt][nj][1] = expf(S[mt][nj][1] - mx[mt][0]);
            S[mt][nj][2] = expf(S[mt][nj][2] - mx[mt][1]);
            S[mt][nj][3] = expf(S[mt][nj][3] - mx[mt][1]);
            sum[mt][0] += S[mt][nj][0] + S[mt][nj][1];
            sum[mt][1] += S[mt][nj][2] + S[mt][nj][3];
        }
#pragma unroll
    for (int mt = 0; mt < 2; mt++)
#pragma unroll
        for (int rr = 0; rr < 2; rr++) {
            sum[mt][rr] += __shfl_xor_sync(0xffffffffu, sum[mt][rr], 1);
            sum[mt][rr] += __shfl_xor_sync(0xffffffffu, sum[mt][rr], 2);
        }

    float O[2][8][4];
#pragma unroll
    for (int mt = 0; mt < 2; mt++)
#pragma unroll
        for (int nj = 0; nj < 8; nj++)
#pragma unroll
            for (int c = 0; c < 4; c++) O[mt][nj][c] = 0.f;

#pragma unroll
    for (int kt = 0; kt < 4; kt++) {
        uint32_t bf[8][2];
#pragma unroll
        for (int g = 0; g < 4; g++) {
            uint32_t r0, r1, r2, r3;
            LDSM_X4(r0, r1, r2, r3, vt + ((nOff[g] + kt * 32) ^ nM[g]));
            bf[2 * g][0] = r0; bf[2 * g][1] = r2;
            bf[2 * g + 1][0] = r1; bf[2 * g + 1][1] = r3;
        }
#pragma unroll
        for (int mt = 0; mt < 2; mt++) {
            uint32_t af[4];
            af[0] = packh2(S[mt][2 * kt][0],     S[mt][2 * kt][1]);
            af[1] = packh2(S[mt][2 * kt][2],     S[mt][2 * kt][3]);
            af[2] = packh2(S[mt][2 * kt + 1][0], S[mt][2 * kt + 1][1]);
            af[3] = packh2(S[mt][2 * kt + 1][2], S[mt][2 * kt + 1][3]);
#pragma unroll
            for (int nj = 0; nj < 8; nj++)
                mma_f16(O[mt][nj], af, bf[nj]);
        }
    }

#pragma unroll
    for (int mt = 0; mt < 2; mt++) {
        const float inv0 = 1.0f / sum[mt][0];
        const float inv1 = 1.0f / sum[mt][1];
        const int row0 = rowbase + mh * 32 + mt * 16 + gid;
#pragma unroll
        for (int nj = 0; nj < 8; nj++) {
            const int col = (h0 + hh) * 64 + nj * 8 + 2 * tig;
            store2(attn + (size_t)row0 * Hq + col,       O[mt][nj][0] * inv0, O[mt][nj][1] * inv0);
            store2(attn + (size_t)(row0 + 8) * Hq + col, O[mt][nj][2] * inv1, O[mt][nj][3] * inv1);
        }
    }
}

// ---------------------------------------------------------------------------
// fp16 GEMM — R10 schedule with DEEPER ring + split prefetch burst.
// CTA 128x256x64, 8 warps (2x4), warp tile 64x64, 1 CTA/SM (255 regs).
// 4-stage cp.async ring (192KB), per-stage wait_group 2 (two groups in
// flight across every barrier); A-prefetch at kk=0, B-prefetch + commit at
// kk=1 (burst split); LDSM(kk+1) before MMA(kk) fragment ping-pong.
// ---------------------------------------------------------------------------
constexpr int BM = 128, BN = 256, BK = 64, NST = 4;
constexpr int A_BYTES = BM * BK * 2;         // 16384
constexpr int B_BYTES = BN * BK * 2;         // 32768
constexpr int STAGE   = A_BYTES + B_BYTES;   // 49152
constexpr int GSMEM   = NST * STAGE;         // 196608

__device__ __forceinline__ void load_stage_A(const __half* __restrict__ gA,
                                             uint32_t sA, int K, int t)
{
#pragma unroll
    for (int i = 0; i < 4; i++) {
        int idx = t + i * 256;          // A: 128 rows x 8 chunks
        int row = idx >> 3, seg = idx & 7;
        uint32_t off = (uint32_t)(row * 128 + seg * 16);
        uint32_t sw  = off ^ ((off >> 3) & 0x70);
        CP_ASYNC16(sA + sw, gA + (size_t)row * K + seg * 8);
    }
}

__device__ __forceinline__ void load_stage_B(const __half* __restrict__ gB,
                                             uint32_t sB, int K, int t)
{
#pragma unroll
    for (int i = 0; i < 8; i++) {
        int idx = t + i * 256;          // B: 256 rows x 8 chunks
        int row = idx >> 3, seg = idx & 7;
        uint32_t off = (uint32_t)(row * 128 + seg * 16);
        uint32_t sw  = off ^ ((off >> 3) & 0x70);
        CP_ASYNC16(sB + sw, gB + (size_t)row * K + seg * 8);
    }
}

// Load one kk's fragments (A: 4 m-tiles, B: 4 groups -> 8 n-tiles).
__device__ __forceinline__ void load_frags(uint32_t af[4][4], uint32_t bf[8][2],
                                           uint32_t sA, uint32_t sB,
                                           uint32_t aOff0, uint32_t bOff0,
                                           uint32_t m, int kk)
{
    const uint32_t ka = (uint32_t)(kk * 32);
#pragma unroll
    for (int mi = 0; mi < 4; mi++)
        LDSM_X4(af[mi][0], af[mi][1], af[mi][2], af[mi][3],
                sA + ((aOff0 + mi * 2048 + ka) ^ m));
#pragma unroll
    for (int g = 0; g < 4; g++) {
        uint32_t r0, r1, r2, r3;
        LDSM_X4(r0, r1, r2, r3, sB + ((bOff0 + g * 2048 + ka) ^ m));
        bf[2 * g][0] = r0; bf[2 * g][1] = r2;
        bf[2 * g + 1][0] = r1; bf[2 * g + 1][1] = r3;
    }
}

__device__ __forceinline__ void do_mma(float acc[4][8][4],
                                       const uint32_t af[4][4], const uint32_t bf[8][2])
{
#pragma unroll
    for (int mi = 0; mi < 4; mi++)
#pragma unroll
        for (int ni = 0; ni < 8; ni++)
            mma_f16(acc[mi][ni], af[mi], bf[ni]);
}

template <int MODE, typename OutT>
__global__ void __launch_bounds__(256)
gemm_f16(const __half* __restrict__ A, const __half* __restrict__ Bw,
         const float* __restrict__ bias, const float* __restrict__ res,
         OutT* __restrict__ C, int N, int K)
{
    extern __shared__ char smem[];
    const uint32_t sb = smem_u32(smem);
    const int t    = threadIdx.x;
    const int lane = t & 31, warp = t >> 5;
    const int wm   = warp & 1, wn = warp >> 1;      // 2 x 4 warp grid
    const int rowA0 = blockIdx.y * BM;
    const int colB0 = blockIdx.x * BN;

    float acc[4][8][4];
#pragma unroll
    for (int mi = 0; mi < 4; mi++)
#pragma unroll
        for (int ni = 0; ni < 8; ni++)
#pragma unroll
            for (int c = 0; c < 4; c++) acc[mi][ni][c] = 0.f;

    const int KT = K / BK;
    const __half* gA = A  + (size_t)rowA0 * K;
    const __half* gB = Bw + (size_t)colB0 * K;

    // prologue: stages 0..2
#pragma unroll
    for (int s = 0; s < NST - 1; s++) {
        load_stage_A(gA + (size_t)s * BK, sb + s * STAGE, K, t);
        load_stage_B(gB + (size_t)s * BK, sb + s * STAGE + A_BYTES, K, t);
        asm volatile("cp.async.commit_group;" ::: "memory");
    }

    // ldmatrix addressing: single mask (row bits = lane&7), fragment index
    // folds into base + i*2048; XOR applied AFTER all adds (verified form).
    const int lrow = lane & 15;
    const int lseg = lane >> 4;
    const uint32_t aM    = (uint32_t)((lane & 7) << 4);
    const uint32_t aOff0 = (uint32_t)((wm * 64 + lrow) * 128 + lseg * 16);
    const uint32_t bOff0 = (uint32_t)((wn * 64 + lrow) * 128 + lseg * 16);

    uint32_t af[2][4][4], bf[2][8][2];

    // wait stage 0, load kk=0 fragments into buffer 0
    asm volatile("cp.async.wait_group %0;" :: "n"(NST - 2) : "memory");
    __syncthreads();
    uint32_t curA = sb;
    uint32_t curB = sb + A_BYTES;
    load_frags(af[0], bf[0], curA, curB, aOff0, bOff0, aM, 0);

    for (int kt = 0; kt < KT; kt++) {
        const int pf = kt + NST - 1;               // prefetch stage index
        const uint32_t pfA = sb + (uint32_t)(pf % NST) * STAGE;

        // kk = 0..2: load next kk's fragments, then MMA current
#pragma unroll
        for (int kk = 0; kk < 3; kk++) {
            load_frags(af[(kk + 1) & 1], bf[(kk + 1) & 1], curA, curB,
                       aOff0, bOff0, aM, kk + 1);
            if (kk == 0 && pf < KT)
                load_stage_A(gA + (size_t)pf * BK, pfA, K, t);
            if (kk == 1) {
                if (pf < KT)
                    load_stage_B(gB + (size_t)pf * BK, pfA + A_BYTES, K, t);
                asm volatile("cp.async.commit_group;" ::: "memory");
            }
            do_mma(acc, af[kk & 1], bf[kk & 1]);
        }
        // stage boundary before last MMA block: next stage's kk=0 fragments
        // load behind MMA(kk=3).
        asm volatile("cp.async.wait_group %0;" :: "n"(NST - 2) : "memory");
        __syncthreads();
        if (kt + 1 < KT) {
            curA = sb + (uint32_t)((kt + 1) % NST) * STAGE;
            curB = curA + A_BYTES;
            load_frags(af[0], bf[0], curA, curB, aOff0, bOff0, aM, 0);
        }
        do_mma(acc, af[1], bf[1]);
    }

    // epilogue
    const int gid = lane >> 2, tig = lane & 3;
#pragma unroll
    for (int mi = 0; mi < 4; mi++)
#pragma unroll
        for (int ni = 0; ni < 8; ni++) {
            const int row = rowA0 + wm * 64 + mi * 16 + gid;
            const int col = colB0 + wn * 64 + ni * 8 + 2 * tig;
            const float b0 = bias[col], b1 = bias[col + 1];
#pragma unroll
            for (int hh = 0; hh < 2; hh++) {
                const int r2 = row + hh * 8;
                float v0 = acc[mi][ni][hh * 2 + 0] + b0;
                float v1 = acc[mi][ni][hh * 2 + 1] + b1;
                if (MODE == 1 || MODE == 3) {
                    v0 += res[(size_t)r2 * N + col];
                    v1 += res[(size_t)r2 * N + col + 1];
                }
                if (MODE == 2) { v0 = gelu_exact(v0); v1 = gelu_exact(v1); }
                int ro = r2;
                if (MODE == 3) {
                    const int bb = r2 >> 12;
                    const int l  = r2 & (Lq - 1);
                    ro = (bb << 12) | ((l + SHIFTq) & (Lq - 1));
                }
                store2(C + (size_t)ro * N + col, v0, v1);
            }
        }
}

// ---------------------------------------------------------------------------
// Launch
// ---------------------------------------------------------------------------
template <typename T>
static T* sym_addr(const void* sym) { void* p; cudaGetSymbolAddress(&p, sym); return (T*)p; }

extern "C" void kernel_launch(void* const* d_in, const int* in_sizes, int n_in,
                              void* d_out, int out_size)
{
    (void)in_sizes; (void)n_in; (void)out_size;
    const float* x     = (const float*)d_in[0];
    const float* ln1_g = (const float*)d_in[1];
    const float* ln1_b = (const float*)d_in[2];
    const float* in_w  = (const float*)d_in[3];
    const float* in_b  = (const float*)d_in[4];
    const float* ow    = (const float*)d_in[5];
    const float* ob    = (const float*)d_in[6];
    const float* ln2_g = (const float*)d_in[7];
    const float* ln2_b = (const float*)d_in[8];
    const float* w1    = (const float*)d_in[9];
    const float* b1    = (const float*)d_in[10];
    const float* w2    = (const float*)d_in[11];
    const float* b2    = (const float*)d_in[12];
    float* out = (float*)d_out;

    float*  xs   = sym_addr<float>(g_xs);
    float*  xsum = sym_addr<float>(g_xsum);
    __half* qin  = sym_addr<__half>(g_qin);
    __half* qkv  = sym_addr<__half>(g_qkv);
    __half* attn = sym_addr<__half>(g_attn);
    __half* z    = sym_addr<__half>(g_z);
    __half* h1   = sym_addr<__half>(g_h1);
    __half* wqkv = sym_addr<__half>(g_wqkv);
    __half* wo   = sym_addr<__half>(g_wo);
    __half* w1h  = sym_addr<__half>(g_w1);
    __half* w2h  = sym_addr<__half>(g_w2);

    cudaFuncSetAttribute(gemm_f16<0, __half>, cudaFuncAttributeMaxDynamicSharedMemorySize, GSMEM);
    cudaFuncSetAttribute(gemm_f16<1, float>,  cudaFuncAttributeMaxDynamicSharedMemorySize, GSMEM);
    cudaFuncSetAttribute(gemm_f16<2, __half>, cudaFuncAttributeMaxDynamicSharedMemorySize, GSMEM);
    cudaFuncSetAttribute(gemm_f16<3, float>,  cudaFuncAttributeMaxDynamicSharedMemorySize, GSMEM);
    cudaFuncSetAttribute(attn_mma_kernel,     cudaFuncAttributeMaxDynamicSharedMemorySize, ATT_SMEM);

    // 0. convert all weights to fp16 (single launch)
    {
        int n0 = 3 * Hq * Hq, n1 = Hq * Hq, n2 = FFq * Hq, n3 = Hq * FFq;
        int tot = (n0 + n1 + n2 + n3) / 4;
        f2h4_kernel<<<(tot + 255) / 256, 256>>>(in_w, wqkv, n0, ow, wo, n1,
                                                w1, w1h, n2, w2, w2h, n3);
    }

    // 1. roll(-SHIFT) + LN1 -> xs (f32), qin (f16)
    ln_kernel<<<Mq, 256>>>(x, ln1_g, ln1_b, xs, qin, SHIFTq);

    // 2. qkv = qin @ in_w^T + in_b          [16384, 3072] f16
    gemm_f16<0, __half><<<dim3(3 * Hq / BN, Mq / BM), 256, GSMEM>>>(
        qin, wqkv, in_b, nullptr, qkv, 3 * Hq, Hq);

    // 3. windowed attention (tensor-core) -> attn (f16)
    attn_mma_kernel<<<dim3(Bq * (Lq / Wq), NHq / 2), 128, ATT_SMEM>>>(qkv, attn);

    // 4. xsum = xs + attn @ ow^T + ob       [16384, 1024] f32
    gemm_f16<1, float><<<dim3(Hq / BN, Mq / BM), 256, GSMEM>>>(
        attn, wo, ob, xs, xsum, Hq, Hq);

    // 5. LN2 -> z (f16)
    ln_kernel<<<Mq, 256>>>(xsum, ln2_g, ln2_b, nullptr, z, 0);

    // 6. h1 = gelu(z @ w1^T + b1)           [16384, 4096] f16
    gemm_f16<2, __half><<<dim3(FFq / BN, Mq / BM), 256, GSMEM>>>(
        z, w1h, b1, nullptr, h1, FFq, Hq);

    // 7. out = roll(+SHIFT)(xsum + h1 @ w2^T + b2)   [16384, 1024] f32
    gemm_f16<3, float><<<dim3(Hq / BN, Mq / BM), 256, GSMEM>>>(
        h1, w2h, b2, xsum, out, Hq, FFq);
}

// round 14
// speedup vs baseline: 1.0541x; 1.0541x over previous
#include <cuda_runtime.h>
#include <cuda_fp16.h>
#include <cstdint>
#include <math.h>

// Problem constants
#define Bq     4
#define Lq     4096
#define Hq     1024
#define NHq    16
#define Wq     64
#define SHIFTq 32
#define FFq    4096
#define HDq    64
#define Mq     (Bq * Lq)   // 16384 rows

// ---------------------------------------------------------------------------
// Scratch (device globals)
// ---------------------------------------------------------------------------
__device__ float  g_xs  [(size_t)Mq * Hq];
__device__ float  g_xsum[(size_t)Mq * Hq];
__device__ __half g_qin [(size_t)Mq * Hq];
__device__ __half g_qkv [(size_t)Mq * 3 * Hq];
__device__ __half g_attn[(size_t)Mq * Hq];
__device__ __half g_z   [(size_t)Mq * Hq];
__device__ __half g_h1  [(size_t)Mq * FFq];
__device__ __half g_wqkv[(size_t)3 * Hq * Hq];
__device__ __half g_wo  [(size_t)Hq * Hq];
__device__ __half g_w1  [(size_t)FFq * Hq];
__device__ __half g_w2  [(size_t)Hq * FFq];

// ---------------------------------------------------------------------------
// Helpers
// ---------------------------------------------------------------------------
__device__ __forceinline__ uint32_t smem_u32(const void* p) {
    uint32_t a;
    asm("{ .reg .u64 t; cvta.to.shared.u64 t, %1; cvt.u32.u64 %0, t; }" : "=r"(a) : "l"(p));
    return a;
}

__device__ __forceinline__ void mma_f16(float c[4], const uint32_t a[4], const uint32_t b[2]) {
    asm volatile(
        "mma.sync.aligned.m16n8k16.row.col.f32.f16.f16.f32 "
        "{%0,%1,%2,%3}, {%4,%5,%6,%7}, {%8,%9}, {%0,%1,%2,%3};\n"
        : "+f"(c[0]), "+f"(c[1]), "+f"(c[2]), "+f"(c[3])
        : "r"(a[0]), "r"(a[1]), "r"(a[2]), "r"(a[3]), "r"(b[0]), "r"(b[1]));
}

#define LDSM_X4(r0, r1, r2, r3, addr) \
    asm volatile("ldmatrix.sync.aligned.m8n8.x4.shared.b16 {%0,%1,%2,%3}, [%4];" \
        : "=r"(r0), "=r"(r1), "=r"(r2), "=r"(r3) : "r"(addr))

#define CP_ASYNC16(dst, src) \
    asm volatile("cp.async.cg.shared.global [%0], [%1], 16;" :: "r"(dst), "l"(src))

__device__ __forceinline__ float gelu_exact(float v) {
    return 0.5f * v * (1.0f + erff(v * 0.70710678118654752f));
}

__device__ __forceinline__ void store2(float* p, float a, float b) {
    *reinterpret_cast<float2*>(p) = make_float2(a, b);
}
__device__ __forceinline__ void store2(__half* p, float a, float b) {
    *reinterpret_cast<__half2*>(p) = __floats2half2_rn(a, b);
}

__device__ __forceinline__ uint32_t packh2(float a, float b) {
    __half2 h = __floats2half2_rn(a, b);
    return *reinterpret_cast<uint32_t*>(&h);
}

// ---------------------------------------------------------------------------
// Fused prep: blocks [0, Mq) do roll(-SHIFT)+LN1; blocks >= Mq convert the
// four weight matrices float->half (concatenated index space). Running both
// in one launch overlaps their independent DRAM streams.
// ---------------------------------------------------------------------------
__global__ void __launch_bounds__(256)
prep_kernel(const float* __restrict__ x, const float* __restrict__ g,
            const float* __restrict__ bb, float* __restrict__ xs_out,
            __half* __restrict__ y,
            const float* __restrict__ s0, __half* __restrict__ d0, int n0,
            const float* __restrict__ s1, __half* __restrict__ d1, int n1,
            const float* __restrict__ s2, __half* __restrict__ d2, int n2,
            const float* __restrict__ s3, __half* __restrict__ d3, int n3)
{
    const int t = threadIdx.x;
    if (blockIdx.x >= Mq) {
        // ---- weight f2h part
        int i = ((blockIdx.x - Mq) * 256 + t) * 4;
        const float* s; __half* d;
        if (i < n0) { s = s0; d = d0; }
        else {
            i -= n0;
            if (i < n1) { s = s1; d = d1; }
            else {
                i -= n1;
                if (i < n2) { s = s2; d = d2; }
                else { i -= n2; s = s3; d = d3; if (i >= n3) return; }
            }
        }
        float4 f = *reinterpret_cast<const float4*>(s + i);
        *reinterpret_cast<__half2*>(d + i)     = __floats2half2_rn(f.x, f.y);
        *reinterpret_cast<__half2*>(d + i + 2) = __floats2half2_rn(f.z, f.w);
        return;
    }

    // ---- LN1 part (row = blockIdx.x), read with roll(-SHIFT)
    const int row = blockIdx.x;
    const int b   = row >> 12;
    const int l   = row & (Lq - 1);
    const int sl  = (l + SHIFTq) & (Lq - 1);
    const float* px = x + ((size_t)(b * Lq + sl)) * Hq;

    float v[4];
    float s = 0.f, sq = 0.f;
#pragma unroll
    for (int i = 0; i < 4; i++) {
        v[i] = px[t + i * 256];
        s  += v[i];
        sq += v[i] * v[i];
    }
#pragma unroll
    for (int o = 16; o > 0; o >>= 1) {
        s  += __shfl_xor_sync(0xffffffffu, s,  o);
        sq += __shfl_xor_sync(0xffffffffu, sq, o);
    }
    __shared__ float ws[8], wq[8];
    const int lane = t & 31, warp = t >> 5;
    if (lane == 0) { ws[warp] = s; wq[warp] = sq; }
    __syncthreads();
    if (t == 0) {
        float S = 0.f, Q = 0.f;
#pragma unroll
        for (int w = 0; w < 8; w++) { S += ws[w]; Q += wq[w]; }
        float mu  = S * (1.0f / Hq);
        float var = Q * (1.0f / Hq) - mu * mu;
        ws[0] = mu;
        wq[0] = rsqrtf(var + 1e-5f);
    }
    __syncthreads();
    const float mu = ws[0], rstd = wq[0];

    __half* py = y + (size_t)row * Hq;
    float* pxs = xs_out + (size_t)row * Hq;
#pragma unroll
    for (int i = 0; i < 4; i++) {
        int c = t + i * 256;
        float xv = v[i];
        py[c] = __float2half((xv - mu) * rstd * g[c] + bb[c]);
        pxs[c] = xv;
    }
}

// ---------------------------------------------------------------------------
// LayerNorm (no roll; for LN2); output half
// ---------------------------------------------------------------------------
__global__ void __launch_bounds__(256)
ln_kernel(const float* __restrict__ x, const float* __restrict__ g,
          const float* __restrict__ bb, __half* __restrict__ y)
{
    const int row = blockIdx.x;
    const float* px = x + (size_t)row * Hq;

    const int t = threadIdx.x;
    float v[4];
    float s = 0.f, sq = 0.f;
#pragma unroll
    for (int i = 0; i < 4; i++) {
        v[i] = px[t + i * 256];
        s  += v[i];
        sq += v[i] * v[i];
    }
#pragma unroll
    for (int o = 16; o > 0; o >>= 1) {
        s  += __shfl_xor_sync(0xffffffffu, s,  o);
        sq += __shfl_xor_sync(0xffffffffu, sq, o);
    }
    __shared__ float ws[8], wq[8];
    const int lane = t & 31, warp = t >> 5;
    if (lane == 0) { ws[warp] = s; wq[warp] = sq; }
    __syncthreads();
    if (t == 0) {
        float S = 0.f, Q = 0.f;
#pragma unroll
        for (int w = 0; w < 8; w++) { S += ws[w]; Q += wq[w]; }
        float mu  = S * (1.0f / Hq);
        float var = Q * (1.0f / Hq) - mu * mu;
        ws[0] = mu;
        wq[0] = rsqrtf(var + 1e-5f);
    }
    __syncthreads();
    const float mu = ws[0], rstd = wq[0];

    __half* py = y + (size_t)row * Hq;
#pragma unroll
    for (int i = 0; i < 4; i++) {
        int c = t + i * 256;
        py[c] = __float2half((v[i] - mu) * rstd * g[c] + bb[c]);
    }
}

// ---------------------------------------------------------------------------
// Tensor-core windowed attention (verified in R8) + 2-CTA/SM hint
// ---------------------------------------------------------------------------
constexpr int ATT_HEAD_BYTES = 24576;            // Q 8K + K 8K + Vt 8K
constexpr int ATT_SMEM = 2 * ATT_HEAD_BYTES;     // 49152

__global__ void __launch_bounds__(128, 2)
attn_mma_kernel(const __half* __restrict__ qkv, __half* __restrict__ attn)
{
    extern __shared__ char asmem[];
    const uint32_t sb = smem_u32(asmem);
    const int bw = blockIdx.x;
    const int b  = bw >> 6, w = bw & 63;
    const int h0 = blockIdx.y * 2;
    const int rowbase = b * Lq + w * 64;
    const int t = threadIdx.x;

#pragma unroll
    for (int hh = 0; hh < 2; hh++) {
        const uint32_t qs = sb + hh * ATT_HEAD_BYTES;
        const uint32_t ks = qs + 8192;
#pragma unroll
        for (int i = 0; i < 4; i++) {
            int idx = t + i * 128;
            int row = idx >> 3, ch = idx & 7;
            uint32_t off = (uint32_t)(row * 128 + ch * 16);
            uint32_t sw = off ^ ((off >> 3) & 0x70);
            const __half* gq = qkv + (size_t)(rowbase + row) * 3072 + (h0 + hh) * 64 + ch * 8;
            CP_ASYNC16(qs + sw, gq);
            CP_ASYNC16(ks + sw, gq + 1024);
        }
    }
    asm volatile("cp.async.commit_group;" ::: "memory");

#pragma unroll
    for (int hh = 0; hh < 2; hh++) {
        char* vtp = asmem + hh * ATT_HEAD_BYTES + 16384;
#pragma unroll
        for (int i = 0; i < 4; i++) {
            int idx = t + i * 128;
            int c = idx >> 3, ch = idx & 7;
            const __half* gv = qkv + (size_t)(rowbase + c) * 3072 + 2048 + (h0 + hh) * 64 + ch * 8;
            uint4 v = *reinterpret_cast<const uint4*>(gv);
            const __half* hv = reinterpret_cast<const __half*>(&v);
#pragma unroll
            for (int j = 0; j < 8; j++) {
                int d = ch * 8 + j;
                uint32_t off = (uint32_t)(d * 128 + c * 2);
                uint32_t sw = off ^ ((off >> 3) & 0x70);
                *reinterpret_cast<__half*>(vtp + sw) = hv[j];
            }
        }
    }
    asm volatile("cp.async.wait_group 0;" ::: "memory");
    __syncthreads();

    const int warp = t >> 5, lane = t & 31;
    const int hh = warp >> 1, mh = warp & 1;
    const uint32_t qs = sb + hh * ATT_HEAD_BYTES;
    const uint32_t ks = qs + 8192;
    const uint32_t vt = qs + 16384;
    const int lrow = lane & 15, lseg = lane >> 4;
    const int gid = lane >> 2, tig = lane & 3;

    uint32_t qOff[2], qM[2], nOff[4], nM[4];
#pragma unroll
    for (int mt = 0; mt < 2; mt++) {
        int row = mh * 32 + mt * 16 + lrow;
        qOff[mt] = (uint32_t)(row * 128 + lseg * 16);
        qM[mt]   = (uint32_t)((row & 7) << 4);
    }
#pragma unroll
    for (int g = 0; g < 4; g++) {
        int row = g * 16 + lrow;
        nOff[g] = (uint32_t)(row * 128 + lseg * 16);
        nM[g]   = (uint32_t)((row & 7) << 4);
    }

    float S[2][8][4];
#pragma unroll
    for (int mt = 0; mt < 2; mt++)
#pragma unroll
        for (int nj = 0; nj < 8; nj++)
#pragma unroll
            for (int c = 0; c < 4; c++) S[mt][nj][c] = 0.f;

#pragma unroll
    for (int kt = 0; kt < 4; kt++) {
        uint32_t af[2][4], bf[8][2];
#pragma unroll
        for (int mt = 0; mt < 2; mt++)
            LDSM_X4(af[mt][0], af[mt][1], af[mt][2], af[mt][3],
                    qs + ((qOff[mt] + kt * 32) ^ qM[mt]));
#pragma unroll
        for (int g = 0; g < 4; g++) {
            uint32_t r0, r1, r2, r3;
            LDSM_X4(r0, r1, r2, r3, ks + ((nOff[g] + kt * 32) ^ nM[g]));
            bf[2 * g][0] = r0; bf[2 * g][1] = r2;
            bf[2 * g + 1][0] = r1; bf[2 * g + 1][1] = r3;
        }
#pragma unroll
        for (int mt = 0; mt < 2; mt++)
#pragma unroll
            for (int nj = 0; nj < 8; nj++)
                mma_f16(S[mt][nj], af[mt], bf[nj]);
    }

    float mx[2][2], sum[2][2];
#pragma unroll
    for (int mt = 0; mt < 2; mt++) { mx[mt][0] = -1e30f; mx[mt][1] = -1e30f; }
#pragma unroll
    for (int mt = 0; mt < 2; mt++)
#pragma unroll
        for (int nj = 0; nj < 8; nj++) {
#pragma unroll
            for (int c = 0; c < 4; c++) S[mt][nj][c] *= 0.125f;
            mx[mt][0] = fmaxf(mx[mt][0], fmaxf(S[mt][nj][0], S[mt][nj][1]));
            mx[mt][1] = fmaxf(mx[mt][1], fmaxf(S[mt][nj][2], S[mt][nj][3]));
        }
#pragma unroll
    for (int mt = 0; mt < 2; mt++)
#pragma unroll
        for (int rr = 0; rr < 2; rr++) {
            mx[mt][rr] = fmaxf(mx[mt][rr], __shfl_xor_sync(0xffffffffu, mx[mt][rr], 1));
            mx[mt][rr] = fmaxf(mx[mt][rr], __shfl_xor_sync(0xffffffffu, mx[mt][rr], 2));
        }
#pragma unroll
    for (int mt = 0; mt < 2; mt++) { sum[mt][0] = 0.f; sum[mt][1] = 0.f; }
#pragma unroll
    for (int mt = 0; mt < 2; mt++)
#pragma unroll
        for (int nj = 0; nj < 8; nj++) {
            S[mt][nj][0] = expf(S[mt][nj][0] - mx[mt][0]);
            S[mt][nj][1] = expf(S[mt][nj][1] - mx[mt][0]);
            S[mt][nj][2] = expf(S[mt][nj][2] - mx[mt][1]);
            S[mt][nj][3] = expf(S[mt][nj][3] - mx[mt][1]);
            sum[mt][0] += S[mt][nj][0] + S[mt][nj][1];
            sum[mt][1] += S[mt][nj][2] + S[mt][nj][3];
        }
#pragma unroll
    for (int mt = 0; mt < 2; mt++)
#pragma unroll
        for (int rr = 0; rr < 2; rr++) {
            sum[mt][rr] += __shfl_xor_sync(0xffffffffu, sum[mt][rr], 1);
            sum[mt][rr] += __shfl_xor_sync(0xffffffffu, sum[mt][rr], 2);
        }

    float O[2][8][4];
#pragma unroll
    for (int mt = 0; mt < 2; mt++)
#pragma unroll
        for (int nj = 0; nj < 8; nj++)
#pragma unroll
            for (int c = 0; c < 4; c++) O[mt][nj][c] = 0.f;

#pragma unroll
    for (int kt = 0; kt < 4; kt++) {
        uint32_t bf[8][2];
#pragma unroll
        for (int g = 0; g < 4; g++) {
            uint32_t r0, r1, r2, r3;
            LDSM_X4(r0, r1, r2, r3, vt + ((nOff[g] + kt * 32) ^ nM[g]));
            bf[2 * g][0] = r0; bf[2 * g][1] = r2;
            bf[2 * g + 1][0] = r1; bf[2 * g + 1][1] = r3;
        }
#pragma unroll
        for (int mt = 0; mt < 2; mt++) {
            uint32_t af[4];
            af[0] = packh2(S[mt][2 * kt][0],     S[mt][2 * kt][1]);
            af[1] = packh2(S[mt][2 * kt][2],     S[mt][2 * kt][3]);
            af[2] = packh2(S[mt][2 * kt + 1][0], S[mt][2 * kt + 1][1]);
            af[3] = packh2(S[mt][2 * kt + 1][2], S[mt][2 * kt + 1][3]);
#pragma unroll
            for (int nj = 0; nj < 8; nj++)
                mma_f16(O[mt][nj], af, bf[nj]);
        }
    }

#pragma unroll
    for (int mt = 0; mt < 2; mt++) {
        const float inv0 = 1.0f / sum[mt][0];
        const float inv1 = 1.0f / sum[mt][1];
        const int row0 = rowbase + mh * 32 + mt * 16 + gid;
#pragma unroll
        for (int nj = 0; nj < 8; nj++) {
            const int col = (h0 + hh) * 64 + nj * 8 + 2 * tig;
            store2(attn + (size_t)row0 * Hq + col,       O[mt][nj][0] * inv0, O[mt][nj][1] * inv0);
            store2(attn + (size_t)(row0 + 8) * Hq + col, O[mt][nj][2] * inv1, O[mt][nj][3] * inv1);
        }
    }
}

// ---------------------------------------------------------------------------
// fp16 GEMM — R12/R10 verified schedule (unchanged): big tile + frag ping-pong.
// CTA 128x256x64, 8 warps (2x4), warp tile 64x64, 1 CTA/SM (255 regs).
// 3-stage cp.async ring (144KB), per-stage wait_group 1.
// ---------------------------------------------------------------------------
constexpr int BM = 128, BN = 256, BK = 64, NST = 3;
constexpr int A_BYTES = BM * BK * 2;         // 16384
constexpr int B_BYTES = BN * BK * 2;         // 32768
constexpr int STAGE   = A_BYTES + B_BYTES;   // 49152
constexpr int GSMEM   = NST * STAGE;         // 147456

__device__ __forceinline__ void gemm_load_stage(const __half* __restrict__ gA,
                                                const __half* __restrict__ gB,
                                                uint32_t sA, uint32_t sB, int K, int t)
{
#pragma unroll
    for (int i = 0; i < 4; i++) {
        int idx = t + i * 256;          // A: 128 rows x 8 chunks
        int row = idx >> 3, seg = idx & 7;
        uint32_t off = (uint32_t)(row * 128 + seg * 16);
        uint32_t sw  = off ^ ((off >> 3) & 0x70);
        CP_ASYNC16(sA + sw, gA + (size_t)row * K + seg * 8);
    }
#pragma unroll
    for (int i = 0; i < 8; i++) {
        int idx = t + i * 256;          // B: 256 rows x 8 chunks
        int row = idx >> 3, seg = idx & 7;
        uint32_t off = (uint32_t)(row * 128 + seg * 16);
        uint32_t sw  = off ^ ((off >> 3) & 0x70);
        CP_ASYNC16(sB + sw, gB + (size_t)row * K + seg * 8);
    }
}

// Load one kk's fragments (A: 4 m-tiles, B: 4 groups -> 8 n-tiles).
__device__ __forceinline__ void load_frags(uint32_t af[4][4], uint32_t bf[8][2],
                                           uint32_t sA, uint32_t sB,
                                           uint32_t aOff0, uint32_t bOff0,
                                           uint32_t m, int kk)
{
    const uint32_t ka = (uint32_t)(kk * 32);
#pragma unroll
    for (int mi = 0; mi < 4; mi++)
        LDSM_X4(af[mi][0], af[mi][1], af[mi][2], af[mi][3],
                sA + ((aOff0 + mi * 2048 + ka) ^ m));
#pragma unroll
    for (int g = 0; g < 4; g++) {
        uint32_t r0, r1, r2, r3;
        LDSM_X4(r0, r1, r2, r3, sB + ((bOff0 + g * 2048 + ka) ^ m));
        bf[2 * g][0] = r0; bf[2 * g][1] = r2;
        bf[2 * g + 1][0] = r1; bf[2 * g + 1][1] = r3;
    }
}

__device__ __forceinline__ void do_mma(float acc[4][8][4],
                                       const uint32_t af[4][4], const uint32_t bf[8][2])
{
#pragma unroll
    for (int mi = 0; mi < 4; mi++)
#pragma unroll
        for (int ni = 0; ni < 8; ni++)
            mma_f16(acc[mi][ni], af[mi], bf[ni]);
}

template <int MODE, typename OutT>
__global__ void __launch_bounds__(256)
gemm_f16(const __half* __restrict__ A, const __half* __restrict__ Bw,
         const float* __restrict__ bias, const float* __restrict__ res,
         OutT* __restrict__ C, int N, int K)
{
    extern __shared__ char smem[];
    const uint32_t sb = smem_u32(smem);
    const int t    = threadIdx.x;
    const int lane = t & 31, warp = t >> 5;
    const int wm   = warp & 1, wn = warp >> 1;      // 2 x 4 warp grid
    const int rowA0 = blockIdx.y * BM;
    const int colB0 = blockIdx.x * BN;

    float acc[4][8][4];
#pragma unroll
    for (int mi = 0; mi < 4; mi++)
#pragma unroll
        for (int ni = 0; ni < 8; ni++)
#pragma unroll
            for (int c = 0; c < 4; c++) acc[mi][ni][c] = 0.f;

    const int KT = K / BK;
    const __half* gA = A  + (size_t)rowA0 * K;
    const __half* gB = Bw + (size_t)colB0 * K;

    // prologue: stages 0..1
#pragma unroll
    for (int s = 0; s < NST - 1; s++) {
        gemm_load_stage(gA + (size_t)s * BK, gB + (size_t)s * BK,
                        sb + s * STAGE, sb + s * STAGE + A_BYTES, K, t);
        asm volatile("cp.async.commit_group;" ::: "memory");
    }

    // ldmatrix addressing: single mask (row bits = lane&7), fragment index
    // folds into base + i*2048; XOR applied AFTER all adds (verified form).
    const int lrow = lane & 15;
    const int lseg = lane >> 4;
    const uint32_t aM    = (uint32_t)((lane & 7) << 4);
    const uint32_t aOff0 = (uint32_t)((wm * 64 + lrow) * 128 + lseg * 16);
    const uint32_t bOff0 = (uint32_t)((wn * 64 + lrow) * 128 + lseg * 16);

    uint32_t af[2][4][4], bf[2][8][2];

    // wait stage 0, load kk=0 fragments into buffer 0
    asm volatile("cp.async.wait_group %0;" :: "n"(NST - 2) : "memory");
    __syncthreads();
    uint32_t curA = sb;
    uint32_t curB = sb + A_BYTES;
    load_frags(af[0], bf[0], curA, curB, aOff0, bOff0, aM, 0);

    for (int kt = 0; kt < KT; kt++) {
        // kk = 0..2: load next kk's fragments, then MMA current
#pragma unroll
        for (int kk = 0; kk < 3; kk++) {
            load_frags(af[(kk + 1) & 1], bf[(kk + 1) & 1], curA, curB,
                       aOff0, bOff0, aM, kk + 1);
            if (kk == 0) {
                const int pf = kt + NST - 1;
                if (pf < KT)
                    gemm_load_stage(gA + (size_t)pf * BK, gB + (size_t)pf * BK,
                                    sb + (pf % NST) * STAGE,
                                    sb + (pf % NST) * STAGE + A_BYTES, K, t);
                asm volatile("cp.async.commit_group;" ::: "memory");
            }
            do_mma(acc, af[kk & 1], bf[kk & 1]);
        }
        // stage boundary before last MMA block: next stage's kk=0 fragments
        // load behind MMA(kk=3).
        asm volatile("cp.async.wait_group %0;" :: "n"(NST - 2) : "memory");
        __syncthreads();
        if (kt + 1 < KT) {
            curA = sb + ((kt + 1) % NST) * STAGE;
            curB = curA + A_BYTES;
            load_frags(af[0], bf[0], curA, curB, aOff0, bOff0, aM, 0);
        }
        do_mma(acc, af[1], bf[1]);
    }

    // epilogue
    const int gid = lane >> 2, tig = lane & 3;
#pragma unroll
    for (int mi = 0; mi < 4; mi++)
#pragma unroll
        for (int ni = 0; ni < 8; ni++) {
            const int row = rowA0 + wm * 64 + mi * 16 + gid;
            const int col = colB0 + wn * 64 + ni * 8 + 2 * tig;
            const float b0 = bias[col], b1 = bias[col + 1];
#pragma unroll
            for (int hh = 0; hh < 2; hh++) {
                const int r2 = row + hh * 8;
                float v0 = acc[mi][ni][hh * 2 + 0] + b0;
                float v1 = acc[mi][ni][hh * 2 + 1] + b1;
                if (MODE == 1 || MODE == 3) {
                    v0 += res[(size_t)r2 * N + col];
                    v1 += res[(size_t)r2 * N + col + 1];
                }
                if (MODE == 2) { v0 = gelu_exact(v0); v1 = gelu_exact(v1); }
                int ro = r2;
                if (MODE == 3) {
                    const int bb = r2 >> 12;
                    const int l  = r2 & (Lq - 1);
                    ro = (bb << 12) | ((l + SHIFTq) & (Lq - 1));
                }
                store2(C + (size_t)ro * N + col, v0, v1);
            }
        }
}

// ---------------------------------------------------------------------------
// Launch
// ---------------------------------------------------------------------------
template <typename T>
static T* sym_addr(const void* sym) { void* p; cudaGetSymbolAddress(&p, sym); return (T*)p; }

extern "C" void kernel_launch(void* const* d_in, const int* in_sizes, int n_in,
                              void* d_out, int out_size)
{
    (void)in_sizes; (void)n_in; (void)out_size;
    const float* x     = (const float*)d_in[0];
    const float* ln1_g = (const float*)d_in[1];
    const float* ln1_b = (const float*)d_in[2];
    const float* in_w  = (const float*)d_in[3];
    const float* in_b  = (const float*)d_in[4];
    const float* ow    = (const float*)d_in[5];
    const float* ob    = (const float*)d_in[6];
    const float* ln2_g = (const float*)d_in[7];
    const float* ln2_b = (const float*)d_in[8];
    const float* w1    = (const float*)d_in[9];
    const float* b1    = (const float*)d_in[10];
    const float* w2    = (const float*)d_in[11];
    const float* b2    = (const float*)d_in[12];
    float* out = (float*)d_out;

    float*  xs   = sym_addr<float>(g_xs);
    float*  xsum = sym_addr<float>(g_xsum);
    __half* qin  = sym_addr<__half>(g_qin);
    __half* qkv  = sym_addr<__half>(g_qkv);
    __half* attn = sym_addr<__half>(g_attn);
    __half* z    = sym_addr<__half>(g_z);
    __half* h1   = sym_addr<__half>(g_h1);
    __half* wqkv = sym_addr<__half>(g_wqkv);
    __half* wo   = sym_addr<__half>(g_wo);
    __half* w1h  = sym_addr<__half>(g_w1);
    __half* w2h  = sym_addr<__half>(g_w2);

    cudaFuncSetAttribute(gemm_f16<0, __half>, cudaFuncAttributeMaxDynamicSharedMemorySize, GSMEM);
    cudaFuncSetAttribute(gemm_f16<1, float>,  cudaFuncAttributeMaxDynamicSharedMemorySize, GSMEM);
    cudaFuncSetAttribute(gemm_f16<2, __half>, cudaFuncAttributeMaxDynamicSharedMemorySize, GSMEM);
    cudaFuncSetAttribute(gemm_f16<3, float>,  cudaFuncAttributeMaxDynamicSharedMemorySize, GSMEM);
    cudaFuncSetAttribute(attn_mma_kernel,     cudaFuncAttributeMaxDynamicSharedMemorySize, ATT_SMEM);

    // 1. fused prep: roll(-SHIFT)+LN1 (blocks 0..Mq) + weight f2h (rest)
    {
        int n0 = 3 * Hq * Hq, n1 = Hq * Hq, n2 = FFq * Hq, n3 = Hq * FFq;
        int wblocks = ((n0 + n1 + n2 + n3) / 4 + 255) / 256;
        prep_kernel<<<Mq + wblocks, 256>>>(x, ln1_g, ln1_b, xs, qin,
                                           in_w, wqkv, n0, ow, wo, n1,
                                           w1, w1h, n2, w2, w2h, n3);
    }

    // 2. qkv = qin @ in_w^T + in_b          [16384, 3072] f16
    gemm_f16<0, __half><<<dim3(3 * Hq / BN, Mq / BM), 256, GSMEM>>>(
        qin, wqkv, in_b, nullptr, qkv, 3 * Hq, Hq);

    // 3. windowed attention (tensor-core) -> attn (f16)
    attn_mma_kernel<<<dim3(Bq * (Lq / Wq), NHq / 2), 128, ATT_SMEM>>>(qkv, attn);

    // 4. xsum = xs + attn @ ow^T + ob       [16384, 1024] f32
    gemm_f16<1, float><<<dim3(Hq / BN, Mq / BM), 256, GSMEM>>>(
        attn, wo, ob, xs, xsum, Hq, Hq);

    // 5. LN2 -> z (f16)
    ln_kernel<<<Mq, 256>>>(xsum, ln2_g, ln2_b, z);

    // 6. h1 = gelu(z @ w1^T + b1)           [16384, 4096] f16
    gemm_f16<2, __half><<<dim3(FFq / BN, Mq / BM), 256, GSMEM>>>(
        z, w1h, b1, nullptr, h1, FFq, Hq);

    // 7. out = roll(+SHIFT)(xsum + h1 @ w2^T + b2)   [16384, 1024] f32
    gemm_f16<3, float><<<dim3(Hq / BN, Mq / BM), 256, GSMEM>>>(
        h1, w2h, b2, xsum, out, Hq, FFq);
}

// round 15
// speedup vs baseline: 1.0626x; 1.0080x over previous
#include <cuda_runtime.h>
#include <cuda_fp16.h>
#include <cstdint>
#include <math.h>

// Problem constants
#define Bq     4
#define Lq     4096
#define Hq     1024
#define NHq    16
#define Wq     64
#define SHIFTq 32
#define FFq    4096
#define HDq    64
#define Mq     (Bq * Lq)   // 16384 rows

// ---------------------------------------------------------------------------
// Scratch (device globals)
// ---------------------------------------------------------------------------
__device__ float  g_xs  [(size_t)Mq * Hq];
__device__ float  g_xsum[(size_t)Mq * Hq];
__device__ __half g_qin [(size_t)Mq * Hq];
__device__ __half g_qkv [(size_t)Mq * 3 * Hq];
__device__ __half g_attn[(size_t)Mq * Hq];
__device__ __half g_z   [(size_t)Mq * Hq];
__device__ __half g_h1  [(size_t)Mq * FFq];
__device__ __half g_wqkv[(size_t)3 * Hq * Hq];
__device__ __half g_wo  [(size_t)Hq * Hq];
__device__ __half g_w1  [(size_t)FFq * Hq];
__device__ __half g_w2  [(size_t)Hq * FFq];

// ---------------------------------------------------------------------------
// Helpers
// ---------------------------------------------------------------------------
__device__ __forceinline__ uint32_t smem_u32(const void* p) {
    uint32_t a;
    asm("{ .reg .u64 t; cvta.to.shared.u64 t, %1; cvt.u32.u64 %0, t; }" : "=r"(a) : "l"(p));
    return a;
}

__device__ __forceinline__ void mma_f16(float c[4], const uint32_t a[4], const uint32_t b[2]) {
    asm volatile(
        "mma.sync.aligned.m16n8k16.row.col.f32.f16.f16.f32 "
        "{%0,%1,%2,%3}, {%4,%5,%6,%7}, {%8,%9}, {%0,%1,%2,%3};\n"
        : "+f"(c[0]), "+f"(c[1]), "+f"(c[2]), "+f"(c[3])
        : "r"(a[0]), "r"(a[1]), "r"(a[2]), "r"(a[3]), "r"(b[0]), "r"(b[1]));
}

#define LDSM_X4(r0, r1, r2, r3, addr) \
    asm volatile("ldmatrix.sync.aligned.m8n8.x4.shared.b16 {%0,%1,%2,%3}, [%4];" \
        : "=r"(r0), "=r"(r1), "=r"(r2), "=r"(r3) : "r"(addr))

#define CP_ASYNC16(dst, src) \
    asm volatile("cp.async.cg.shared.global [%0], [%1], 16;" :: "r"(dst), "l"(src))

__device__ __forceinline__ float gelu_exact(float v) {
    return 0.5f * v * (1.0f + erff(v * 0.70710678118654752f));
}

__device__ __forceinline__ void store2(float* p, float a, float b) {
    *reinterpret_cast<float2*>(p) = make_float2(a, b);
}
__device__ __forceinline__ void store2(__half* p, float a, float b) {
    *reinterpret_cast<__half2*>(p) = __floats2half2_rn(a, b);
}

__device__ __forceinline__ uint32_t packh2(float a, float b) {
    __half2 h = __floats2half2_rn(a, b);
    return *reinterpret_cast<uint32_t*>(&h);
}

// ---------------------------------------------------------------------------
// Fused prep: blocks [0, Mq) do roll(-SHIFT)+LN1; blocks >= Mq convert the
// four weight matrices float->half. Vectorized: float4 loads, half2 stores.
// ---------------------------------------------------------------------------
__global__ void __launch_bounds__(256)
prep_kernel(const float* __restrict__ x, const float* __restrict__ g,
            const float* __restrict__ bb, float* __restrict__ xs_out,
            __half* __restrict__ y,
            const float* __restrict__ s0, __half* __restrict__ d0, int n0,
            const float* __restrict__ s1, __half* __restrict__ d1, int n1,
            const float* __restrict__ s2, __half* __restrict__ d2, int n2,
            const float* __restrict__ s3, __half* __restrict__ d3, int n3)
{
    const int t = threadIdx.x;
    if (blockIdx.x >= Mq) {
        int i = ((blockIdx.x - Mq) * 256 + t) * 4;
        const float* s; __half* d;
        if (i < n0) { s = s0; d = d0; }
        else {
            i -= n0;
            if (i < n1) { s = s1; d = d1; }
            else {
                i -= n1;
                if (i < n2) { s = s2; d = d2; }
                else { i -= n2; s = s3; d = d3; if (i >= n3) return; }
            }
        }
        float4 f = *reinterpret_cast<const float4*>(s + i);
        *reinterpret_cast<__half2*>(d + i)     = __floats2half2_rn(f.x, f.y);
        *reinterpret_cast<__half2*>(d + i + 2) = __floats2half2_rn(f.z, f.w);
        return;
    }

    // LN1 part: row = blockIdx.x, read with roll(-SHIFT). Thread handles 4
    // consecutive elements at c = t*4 (float4 load, half2/float4 stores).
    const int row = blockIdx.x;
    const int b   = row >> 12;
    const int l   = row & (Lq - 1);
    const int sl  = (l + SHIFTq) & (Lq - 1);
    const float* px = x + ((size_t)(b * Lq + sl)) * Hq;

    const float4 f = *reinterpret_cast<const float4*>(px + t * 4);
    float s  = f.x + f.y + f.z + f.w;
    float sq = f.x * f.x + f.y * f.y + f.z * f.z + f.w * f.w;
#pragma unroll
    for (int o = 16; o > 0; o >>= 1) {
        s  += __shfl_xor_sync(0xffffffffu, s,  o);
        sq += __shfl_xor_sync(0xffffffffu, sq, o);
    }
    __shared__ float ws[8], wq[8];
    const int lane = t & 31, warp = t >> 5;
    if (lane == 0) { ws[warp] = s; wq[warp] = sq; }
    __syncthreads();
    if (t == 0) {
        float S = 0.f, Q = 0.f;
#pragma unroll
        for (int w = 0; w < 8; w++) { S += ws[w]; Q += wq[w]; }
        float mu  = S * (1.0f / Hq);
        float var = Q * (1.0f / Hq) - mu * mu;
        ws[0] = mu;
        wq[0] = rsqrtf(var + 1e-5f);
    }
    __syncthreads();
    const float mu = ws[0], rstd = wq[0];

    const int c = t * 4;
    const float4 gg = *reinterpret_cast<const float4*>(g + c);
    const float4 bv = *reinterpret_cast<const float4*>(bb + c);
    __half* py = y + (size_t)row * Hq + c;
    *reinterpret_cast<__half2*>(py)     = __floats2half2_rn((f.x - mu) * rstd * gg.x + bv.x,
                                                            (f.y - mu) * rstd * gg.y + bv.y);
    *reinterpret_cast<__half2*>(py + 2) = __floats2half2_rn((f.z - mu) * rstd * gg.z + bv.z,
                                                            (f.w - mu) * rstd * gg.w + bv.w);
    *reinterpret_cast<float4*>(xs_out + (size_t)row * Hq + c) = f;
}

// ---------------------------------------------------------------------------
// LayerNorm (no roll; LN2). float4 loads, half2 stores.
// ---------------------------------------------------------------------------
__global__ void __launch_bounds__(256)
ln_kernel(const float* __restrict__ x, const float* __restrict__ g,
          const float* __restrict__ bb, __half* __restrict__ y)
{
    const int row = blockIdx.x;
    const int t = threadIdx.x;
    const float4 f = *reinterpret_cast<const float4*>(x + (size_t)row * Hq + t * 4);
    float s  = f.x + f.y + f.z + f.w;
    float sq = f.x * f.x + f.y * f.y + f.z * f.z + f.w * f.w;
#pragma unroll
    for (int o = 16; o > 0; o >>= 1) {
        s  += __shfl_xor_sync(0xffffffffu, s,  o);
        sq += __shfl_xor_sync(0xffffffffu, sq, o);
    }
    __shared__ float ws[8], wq[8];
    const int lane = t & 31, warp = t >> 5;
    if (lane == 0) { ws[warp] = s; wq[warp] = sq; }
    __syncthreads();
    if (t == 0) {
        float S = 0.f, Q = 0.f;
#pragma unroll
        for (int w = 0; w < 8; w++) { S += ws[w]; Q += wq[w]; }
        float mu  = S * (1.0f / Hq);
        float var = Q * (1.0f / Hq) - mu * mu;
        ws[0] = mu;
        wq[0] = rsqrtf(var + 1e-5f);
    }
    __syncthreads();
    const float mu = ws[0], rstd = wq[0];

    const int c = t * 4;
    const float4 gg = *reinterpret_cast<const float4*>(g + c);
    const float4 bv = *reinterpret_cast<const float4*>(bb + c);
    __half* py = y + (size_t)row * Hq + c;
    *reinterpret_cast<__half2*>(py)     = __floats2half2_rn((f.x - mu) * rstd * gg.x + bv.x,
                                                            (f.y - mu) * rstd * gg.y + bv.y);
    *reinterpret_cast<__half2*>(py + 2) = __floats2half2_rn((f.z - mu) * rstd * gg.z + bv.z,
                                                            (f.w - mu) * rstd * gg.w + bv.w);
}

// ---------------------------------------------------------------------------
// Tensor-core windowed attention. V-transpose now uses paired-row half2
// stores (conflict-free within warp: ch const per warp, addr = base + 4p).
// ---------------------------------------------------------------------------
constexpr int ATT_HEAD_BYTES = 24576;            // Q 8K + K 8K + Vt 8K
constexpr int ATT_SMEM = 2 * ATT_HEAD_BYTES;     // 49152

__global__ void __launch_bounds__(128, 2)
attn_mma_kernel(const __half* __restrict__ qkv, __half* __restrict__ attn)
{
    extern __shared__ char asmem[];
    const uint32_t sb = smem_u32(asmem);
    const int bw = blockIdx.x;
    const int b  = bw >> 6, w = bw & 63;
    const int h0 = blockIdx.y * 2;
    const int rowbase = b * Lq + w * 64;
    const int t = threadIdx.x;

#pragma unroll
    for (int hh = 0; hh < 2; hh++) {
        const uint32_t qs = sb + hh * ATT_HEAD_BYTES;
        const uint32_t ks = qs + 8192;
#pragma unroll
        for (int i = 0; i < 4; i++) {
            int idx = t + i * 128;
            int row = idx >> 3, ch = idx & 7;
            uint32_t off = (uint32_t)(row * 128 + ch * 16);
            uint32_t sw = off ^ ((off >> 3) & 0x70);
            const __half* gq = qkv + (size_t)(rowbase + row) * 3072 + (h0 + hh) * 64 + ch * 8;
            CP_ASYNC16(qs + sw, gq);
            CP_ASYNC16(ks + sw, gq + 1024);
        }
    }
    asm volatile("cp.async.commit_group;" ::: "memory");

    // V: load row pairs, store transposed half2 (conflict-free)
#pragma unroll
    for (int hh = 0; hh < 2; hh++) {
        char* vtp = asmem + hh * ATT_HEAD_BYTES + 16384;
#pragma unroll
        for (int j = 0; j < 2; j++) {
            int item = t + j * 128;          // 0..255
            int p  = item & 31;              // c-pair 0..31
            int ch = item >> 5;              // 0..7
            const __half* gv0 = qkv + (size_t)(rowbase + 2 * p) * 3072 + 2048 + (h0 + hh) * 64 + ch * 8;
            uint4 v0 = *reinterpret_cast<const uint4*>(gv0);
            uint4 v1 = *reinterpret_cast<const uint4*>(gv0 + 3072);
            const __half* h0p = reinterpret_cast<const __half*>(&v0);
            const __half* h1p = reinterpret_cast<const __half*>(&v1);
#pragma unroll
            for (int k = 0; k < 8; k++) {
                int d = ch * 8 + k;
                uint32_t off = (uint32_t)(d * 128 + p * 4);
                uint32_t sw  = off ^ ((off >> 3) & 0x70);
                __half2 pr; pr.x = h0p[k]; pr.y = h1p[k];
                *reinterpret_cast<__half2*>(vtp + sw) = pr;
            }
        }
    }
    asm volatile("cp.async.wait_group 0;" ::: "memory");
    __syncthreads();

    const int warp = t >> 5, lane = t & 31;
    const int hh = warp >> 1, mh = warp & 1;
    const uint32_t qs = sb + hh * ATT_HEAD_BYTES;
    const uint32_t ks = qs + 8192;
    const uint32_t vt = qs + 16384;
    const int lrow = lane & 15, lseg = lane >> 4;
    const int gid = lane >> 2, tig = lane & 3;

    uint32_t qOff[2], qM[2], nOff[4], nM[4];
#pragma unroll
    for (int mt = 0; mt < 2; mt++) {
        int row = mh * 32 + mt * 16 + lrow;
        qOff[mt] = (uint32_t)(row * 128 + lseg * 16);
        qM[mt]   = (uint32_t)((row & 7) << 4);
    }
#pragma unroll
    for (int g = 0; g < 4; g++) {
        int row = g * 16 + lrow;
        nOff[g] = (uint32_t)(row * 128 + lseg * 16);
        nM[g]   = (uint32_t)((row & 7) << 4);
    }

    float S[2][8][4];
#pragma unroll
    for (int mt = 0; mt < 2; mt++)
#pragma unroll
        for (int nj = 0; nj < 8; nj++)
#pragma unroll
            for (int c = 0; c < 4; c++) S[mt][nj][c] = 0.f;

#pragma unroll
    for (int kt = 0; kt < 4; kt++) {
        uint32_t af[2][4], bf[8][2];
#pragma unroll
        for (int mt = 0; mt < 2; mt++)
            LDSM_X4(af[mt][0], af[mt][1], af[mt][2], af[mt][3],
                    qs + ((qOff[mt] + kt * 32) ^ qM[mt]));
#pragma unroll
        for (int g = 0; g < 4; g++) {
            uint32_t r0, r1, r2, r3;
            LDSM_X4(r0, r1, r2, r3, ks + ((nOff[g] + kt * 32) ^ nM[g]));
            bf[2 * g][0] = r0; bf[2 * g][1] = r2;
            bf[2 * g + 1][0] = r1; bf[2 * g + 1][1] = r3;
        }
#pragma unroll
        for (int mt = 0; mt < 2; mt++)
#pragma unroll
            for (int nj = 0; nj < 8; nj++)
                mma_f16(S[mt][nj], af[mt], bf[nj]);
    }

    float mx[2][2], sum[2][2];
#pragma unroll
    for (int mt = 0; mt < 2; mt++) { mx[mt][0] = -1e30f; mx[mt][1] = -1e30f; }
#pragma unroll
    for (int mt = 0; mt < 2; mt++)
#pragma unroll
        for (int nj = 0; nj < 8; nj++) {
#pragma unroll
            for (int c = 0; c < 4; c++) S[mt][nj][c] *= 0.125f;
            mx[mt][0] = fmaxf(mx[mt][0], fmaxf(S[mt][nj][0], S[mt][nj][1]));
            mx[mt][1] = fmaxf(mx[mt][1], fmaxf(S[mt][nj][2], S[mt][nj][3]));
        }
#pragma unroll
    for (int mt = 0; mt < 2; mt++)
#pragma unroll
        for (int rr = 0; rr < 2; rr++) {
            mx[mt][rr] = fmaxf(mx[mt][rr], __shfl_xor_sync(0xffffffffu, mx[mt][rr], 1));
            mx[mt][rr] = fmaxf(mx[mt][rr], __shfl_xor_sync(0xffffffffu, mx[mt][rr], 2));
        }
#pragma unroll
    for (int mt = 0; mt < 2; mt++) { sum[mt][0] = 0.f; sum[mt][1] = 0.f; }
#pragma unroll
    for (int mt = 0; mt < 2; mt++)
#pragma unroll
        for (int nj = 0; nj < 8; nj++) {
            S[mt][nj][0] = __expf(S[mt][nj][0] - mx[mt][0]);
            S[mt][nj][1] = __expf(S[mt][nj][1] - mx[mt][0]);
            S[mt][nj][2] = __expf(S[mt][nj][2] - mx[mt][1]);
            S[mt][nj][3] = __expf(S[mt][nj][3] - mx[mt][1]);
            sum[mt][0] += S[mt][nj][0] + S[mt][nj][1];
            sum[mt][1] += S[mt][nj][2] + S[mt][nj][3];
        }
#pragma unroll
    for (int mt = 0; mt < 2; mt++)
#pragma unroll
        for (int rr = 0; rr < 2; rr++) {
            sum[mt][rr] += __shfl_xor_sync(0xffffffffu, sum[mt][rr], 1);
            sum[mt][rr] += __shfl_xor_sync(0xffffffffu, sum[mt][rr], 2);
        }

    float O[2][8][4];
#pragma unroll
    for (int mt = 0; mt < 2; mt++)
#pragma unroll
        for (int nj = 0; nj < 8; nj++)
#pragma unroll
            for (int c = 0; c < 4; c++) O[mt][nj][c] = 0.f;

#pragma unroll
    for (int kt = 0; kt < 4; kt++) {
        uint32_t bf[8][2];
#pragma unroll
        for (int g = 0; g < 4; g++) {
            uint32_t r0, r1, r2, r3;
            LDSM_X4(r0, r1, r2, r3, vt + ((nOff[g] + kt * 32) ^ nM[g]));
            bf[2 * g][0] = r0; bf[2 * g][1] = r2;
            bf[2 * g + 1][0] = r1; bf[2 * g + 1][1] = r3;
        }
#pragma unroll
        for (int mt = 0; mt < 2; mt++) {
            uint32_t af[4];
            af[0] = packh2(S[mt][2 * kt][0],     S[mt][2 * kt][1]);
            af[1] = packh2(S[mt][2 * kt][2],     S[mt][2 * kt][3]);
            af[2] = packh2(S[mt][2 * kt + 1][0], S[mt][2 * kt + 1][1]);
            af[3] = packh2(S[mt][2 * kt + 1][2], S[mt][2 * kt + 1][3]);
#pragma unroll
            for (int nj = 0; nj < 8; nj++)
                mma_f16(O[mt][nj], af, bf[nj]);
        }
    }

#pragma unroll
    for (int mt = 0; mt < 2; mt++) {
        const float inv0 = 1.0f / sum[mt][0];
        const float inv1 = 1.0f / sum[mt][1];
        const int row0 = rowbase + mh * 32 + mt * 16 + gid;
#pragma unroll
        for (int nj = 0; nj < 8; nj++) {
            const int col = (h0 + hh) * 64 + nj * 8 + 2 * tig;
            store2(attn + (size_t)row0 * Hq + col,       O[mt][nj][0] * inv0, O[mt][nj][1] * inv0);
            store2(attn + (size_t)(row0 + 8) * Hq + col, O[mt][nj][2] * inv1, O[mt][nj][3] * inv1);
        }
    }
}

// ---------------------------------------------------------------------------
// fp16 GEMM — R12/R10 verified schedule (unchanged).
// ---------------------------------------------------------------------------
constexpr int BM = 128, BN = 256, BK = 64, NST = 3;
constexpr int A_BYTES = BM * BK * 2;
constexpr int B_BYTES = BN * BK * 2;
constexpr int STAGE   = A_BYTES + B_BYTES;
constexpr int GSMEM   = NST * STAGE;

__device__ __forceinline__ void gemm_load_stage(const __half* __restrict__ gA,
                                                const __half* __restrict__ gB,
                                                uint32_t sA, uint32_t sB, int K, int t)
{
#pragma unroll
    for (int i = 0; i < 4; i++) {
        int idx = t + i * 256;
        int row = idx >> 3, seg = idx & 7;
        uint32_t off = (uint32_t)(row * 128 + seg * 16);
        uint32_t sw  = off ^ ((off >> 3) & 0x70);
        CP_ASYNC16(sA + sw, gA + (size_t)row * K + seg * 8);
    }
#pragma unroll
    for (int i = 0; i < 8; i++) {
        int idx = t + i * 256;
        int row = idx >> 3, seg = idx & 7;
        uint32_t off = (uint32_t)(row * 128 + seg * 16);
        uint32_t sw  = off ^ ((off >> 3) & 0x70);
        CP_ASYNC16(sB + sw, gB + (size_t)row * K + seg * 8);
    }
}

__device__ __forceinline__ void load_frags(uint32_t af[4][4], uint32_t bf[8][2],
                                           uint32_t sA, uint32_t sB,
                                           uint32_t aOff0, uint32_t bOff0,
                                           uint32_t m, int kk)
{
    const uint32_t ka = (uint32_t)(kk * 32);
#pragma unroll
    for (int mi = 0; mi < 4; mi++)
        LDSM_X4(af[mi][0], af[mi][1], af[mi][2], af[mi][3],
                sA + ((aOff0 + mi * 2048 + ka) ^ m));
#pragma unroll
    for (int g = 0; g < 4; g++) {
        uint32_t r0, r1, r2, r3;
        LDSM_X4(r0, r1, r2, r3, sB + ((bOff0 + g * 2048 + ka) ^ m));
        bf[2 * g][0] = r0; bf[2 * g][1] = r2;
        bf[2 * g + 1][0] = r1; bf[2 * g + 1][1] = r3;
    }
}

__device__ __forceinline__ void do_mma(float acc[4][8][4],
                                       const uint32_t af[4][4], const uint32_t bf[8][2])
{
#pragma unroll
    for (int mi = 0; mi < 4; mi++)
#pragma unroll
        for (int ni = 0; ni < 8; ni++)
            mma_f16(acc[mi][ni], af[mi], bf[ni]);
}

template <int MODE, typename OutT>
__global__ void __launch_bounds__(256)
gemm_f16(const __half* __restrict__ A, const __half* __restrict__ Bw,
         const float* __restrict__ bias, const float* __restrict__ res,
         OutT* __restrict__ C, int N, int K)
{
    extern __shared__ char smem[];
    const uint32_t sb = smem_u32(smem);
    const int t    = threadIdx.x;
    const int lane = t & 31, warp = t >> 5;
    const int wm   = warp & 1, wn = warp >> 1;
    const int rowA0 = blockIdx.y * BM;
    const int colB0 = blockIdx.x * BN;

    float acc[4][8][4];
#pragma unroll
    for (int mi = 0; mi < 4; mi++)
#pragma unroll
        for (int ni = 0; ni < 8; ni++)
#pragma unroll
            for (int c = 0; c < 4; c++) acc[mi][ni][c] = 0.f;

    const int KT = K / BK;
    const __half* gA = A  + (size_t)rowA0 * K;
    const __half* gB = Bw + (size_t)colB0 * K;

#pragma unroll
    for (int s = 0; s < NST - 1; s++) {
        gemm_load_stage(gA + (size_t)s * BK, gB + (size_t)s * BK,
                        sb + s * STAGE, sb + s * STAGE + A_BYTES, K, t);
        asm volatile("cp.async.commit_group;" ::: "memory");
    }

    const int lrow = lane & 15;
    const int lseg = lane >> 4;
    const uint32_t aM    = (uint32_t)((lane & 7) << 4);
    const uint32_t aOff0 = (uint32_t)((wm * 64 + lrow) * 128 + lseg * 16);
    const uint32_t bOff0 = (uint32_t)((wn * 64 + lrow) * 128 + lseg * 16);

    uint32_t af[2][4][4], bf[2][8][2];

    asm volatile("cp.async.wait_group %0;" :: "n"(NST - 2) : "memory");
    __syncthreads();
    uint32_t curA = sb;
    uint32_t curB = sb + A_BYTES;
    load_frags(af[0], bf[0], curA, curB, aOff0, bOff0, aM, 0);

    for (int kt = 0; kt < KT; kt++) {
#pragma unroll
        for (int kk = 0; kk < 3; kk++) {
            load_frags(af[(kk + 1) & 1], bf[(kk + 1) & 1], curA, curB,
                       aOff0, bOff0, aM, kk + 1);
            if (kk == 0) {
                const int pf = kt + NST - 1;
                if (pf < KT)
                    gemm_load_stage(gA + (size_t)pf * BK, gB + (size_t)pf * BK,
                                    sb + (pf % NST) * STAGE,
                                    sb + (pf % NST) * STAGE + A_BYTES, K, t);
                asm volatile("cp.async.commit_group;" ::: "memory");
            }
            do_mma(acc, af[kk & 1], bf[kk & 1]);
        }
        asm volatile("cp.async.wait_group %0;" :: "n"(NST - 2) : "memory");
        __syncthreads();
        if (kt + 1 < KT) {
            curA = sb + ((kt + 1) % NST) * STAGE;
            curB = curA + A_BYTES;
            load_frags(af[0], bf[0], curA, curB, aOff0, bOff0, aM, 0);
        }
        do_mma(acc, af[1], bf[1]);
    }

    const int gid = lane >> 2, tig = lane & 3;
#pragma unroll
    for (int mi = 0; mi < 4; mi++)
#pragma unroll
        for (int ni = 0; ni < 8; ni++) {
            const int row = rowA0 + wm * 64 + mi * 16 + gid;
            const int col = colB0 + wn * 64 + ni * 8 + 2 * tig;
            const float b0 = bias[col], b1 = bias[col + 1];
#pragma unroll
            for (int hh = 0; hh < 2; hh++) {
                const int r2 = row + hh * 8;
                float v0 = acc[mi][ni][hh * 2 + 0] + b0;
                float v1 = acc[mi][ni][hh * 2 + 1] + b1;
                if (MODE == 1 || MODE == 3) {
                    v0 += res[(size_t)r2 * N + col];
                    v1 += res[(size_t)r2 * N + col + 1];
                }
                if (MODE == 2) { v0 = gelu_exact(v0); v1 = gelu_exact(v1); }
                int ro = r2;
                if (MODE == 3) {
                    const int bb = r2 >> 12;
                    const int l  = r2 & (Lq - 1);
                    ro = (bb << 12) | ((l + SHIFTq) & (Lq - 1));
                }
                store2(C + (size_t)ro * N + col, v0, v1);
            }
        }
}

// ---------------------------------------------------------------------------
// Launch
// ---------------------------------------------------------------------------
template <typename T>
static T* sym_addr(const void* sym) { void* p; cudaGetSymbolAddress(&p, sym); return (T*)p; }

extern "C" void kernel_launch(void* const* d_in, const int* in_sizes, int n_in,
                              void* d_out, int out_size)
{
    (void)in_sizes; (void)n_in; (void)out_size;
    const float* x     = (const float*)d_in[0];
    const float* ln1_g = (const float*)d_in[1];
    const float* ln1_b = (const float*)d_in[2];
    const float* in_w  = (const float*)d_in[3];
    const float* in_b  = (const float*)d_in[4];
    const float* ow    = (const float*)d_in[5];
    const float* ob    = (const float*)d_in[6];
    const float* ln2_g = (const float*)d_in[7];
    const float* ln2_b = (const float*)d_in[8];
    const float* w1    = (const float*)d_in[9];
    const float* b1    = (const float*)d_in[10];
    const float* w2    = (const float*)d_in[11];
    const float* b2    = (const float*)d_in[12];
    float* out = (float*)d_out;

    float*  xs   = sym_addr<float>(g_xs);
    float*  xsum = sym_addr<float>(g_xsum);
    __half* qin  = sym_addr<__half>(g_qin);
    __half* qkv  = sym_addr<__half>(g_qkv);
    __half* attn = sym_addr<__half>(g_attn);
    __half* z    = sym_addr<__half>(g_z);
    __half* h1   = sym_addr<__half>(g_h1);
    __half* wqkv = sym_addr<__half>(g_wqkv);
    __half* wo   = sym_addr<__half>(g_wo);
    __half* w1h  = sym_addr<__half>(g_w1);
    __half* w2h  = sym_addr<__half>(g_w2);

    cudaFuncSetAttribute(gemm_f16<0, __half>, cudaFuncAttributeMaxDynamicSharedMemorySize, GSMEM);
    cudaFuncSetAttribute(gemm_f16<1, float>,  cudaFuncAttributeMaxDynamicSharedMemorySize, GSMEM);
    cudaFuncSetAttribute(gemm_f16<2, __half>, cudaFuncAttributeMaxDynamicSharedMemorySize, GSMEM);
    cudaFuncSetAttribute(gemm_f16<3, float>,  cudaFuncAttributeMaxDynamicSharedMemorySize, GSMEM);
    cudaFuncSetAttribute(attn_mma_kernel,     cudaFuncAttributeMaxDynamicSharedMemorySize, ATT_SMEM);

    // 1. fused prep: roll(-SHIFT)+LN1 (blocks 0..Mq) + weight f2h (rest)
    {
        int n0 = 3 * Hq * Hq, n1 = Hq * Hq, n2 = FFq * Hq, n3 = Hq * FFq;
        int wblocks = ((n0 + n1 + n2 + n3) / 4 + 255) / 256;
        prep_kernel<<<Mq + wblocks, 256>>>(x, ln1_g, ln1_b, xs, qin,
                                           in_w, wqkv, n0, ow, wo, n1,
                                           w1, w1h, n2, w2, w2h, n3);
    }

    // 2. qkv = qin @ in_w^T + in_b          [16384, 3072] f16
    gemm_f16<0, __half><<<dim3(3 * Hq / BN, Mq / BM), 256, GSMEM>>>(
        qin, wqkv, in_b, nullptr, qkv, 3 * Hq, Hq);

    // 3. windowed attention (tensor-core) -> attn (f16)
    attn_mma_kernel<<<dim3(Bq * (Lq / Wq), NHq / 2), 128, ATT_SMEM>>>(qkv, attn);

    // 4. xsum = xs + attn @ ow^T + ob       [16384, 1024] f32
    gemm_f16<1, float><<<dim3(Hq / BN, Mq / BM), 256, GSMEM>>>(
        attn, wo, ob, xs, xsum, Hq, Hq);

    // 5. LN2 -> z (f16)
    ln_kernel<<<Mq, 256>>>(xsum, ln2_g, ln2_b, z);

    // 6. h1 = gelu(z @ w1^T + b1)           [16384, 4096] f16
    gemm_f16<2, __half><<<dim3(FFq / BN, Mq / BM), 256, GSMEM>>>(
        z, w1h, b1, nullptr, h1, FFq, Hq);

    // 7. out = roll(+SHIFT)(xsum + h1 @ w2^T + b2)   [16384, 1024] f32
    gemm_f16<3, float><<<dim3(Hq / BN, Mq / BM), 256, GSMEM>>>(
        h1, w2h, b2, xsum, out, Hq, FFq);
}